// round 5
// baseline (speedup 1.0000x reference)
#include <cuda_runtime.h>

#define BB   2
#define HH   8
#define PP   128
#define HIDD 1024
#define KWIN 128

__device__ float    g_y[BB][HH][PP];   // SSD output at t = T-1
__device__ unsigned g_cnt[BB];         // monotonic arrival counter (never reset)

__global__ void __launch_bounds__(256, 1)
k_fused(const float* __restrict__ hidden,
        const float* __restrict__ dt_W,
        const float* __restrict__ dt_b,
        const float* __restrict__ g_W,
        const float* __restrict__ g_bv,
        const float* __restrict__ A_log,
        const float* __restrict__ Dv,
        const float* __restrict__ dt_bias,
        const float* __restrict__ norm_w,
        const float* __restrict__ o_W,
        const float* __restrict__ o_bv,
        float* __restrict__ out, int T) {
    int b = blockIdx.x >> 3, h = blockIdx.x & 7;
    int tid = threadIdx.x, warp = tid >> 5, lane = tid & 31;
    int q = tid & 127, hf = tid >> 7;
    int s0 = T - KWIN;

    __shared__ float4  wsh4[HIDD / 4];     // dt_W[h]
    __shared__ float4  xlast4[PP / 4];     // own-head slice of last row
    __shared__ float   dte[KWIN], dots[KWIN], sc[KWIN], wv[KWIN];
    __shared__ float   part[2][PP];
    __shared__ float   silu_sh[HH];
    __shared__ float   red[8];
    __shared__ float   scsh;
    __shared__ float   zsh[PP];
    __shared__ unsigned my_sh;

    // ---- Prefetch o_W tile into registers: 512B/thread of cold DRAM whose
    // latency overlaps the entire window phase below. Values consumed last. ----
    float Wreg[64];
    {
        const float* Wp = o_W + ((size_t)h * PP + hf * 64) * PP + q;
        #pragma unroll
        for (int i = 0; i < 64; i++) Wreg[i] = Wp[(size_t)i * PP];
    }

    {
        const float4* w4 = (const float4*)(dt_W + (size_t)h * HIDD);
        for (int i = tid; i < HIDD / 4; i += 256) wsh4[i] = w4[i];
        const float4* xl4 = (const float4*)(hidden + ((size_t)b * T + T - 1) * HIDD + h * PP);
        if (tid < PP / 4) xlast4[tid] = xl4[tid];
    }
    __syncthreads();

    float Ah   = -__expf(A_log[h]);
    float bias = dt_b[h] + dt_bias[h];

    // ---- Phase A: dte[s] (full-row dot with dt_W[h]) + dots[s] (head slice) ----
    for (int s = warp; s < KWIN; s += 8) {
        const float4* xr4 = (const float4*)(hidden + ((size_t)b * T + s0 + s) * HIDD);
        float v = 0.f;
        #pragma unroll
        for (int k = 0; k < 8; k++) {
            float4 a = xr4[lane + 32 * k], w = wsh4[lane + 32 * k];
            v += a.x * w.x + a.y * w.y + a.z * w.z + a.w * w.w;
        }
        float4 ahd = xr4[h * (PP / 4) + lane], xw = xlast4[lane];
        float d = ahd.x * xw.x + ahd.y * xw.y + ahd.z * xw.z + ahd.w * xw.w;
        #pragma unroll
        for (int o = 16; o > 0; o >>= 1) {
            v += __shfl_xor_sync(0xffffffffu, v, o);
            d += __shfl_xor_sync(0xffffffffu, d, o);
        }
        if (lane == 0) { dte[s] = v + bias; dots[s] = d; }
    }
    __syncthreads();

    // ---- Phase B: suffix sum of dA via reversed inclusive prefix scan ----
    if (tid < KWIN) sc[tid] = dte[KWIN - 1 - tid] * Ah;
    __syncthreads();
    for (int off = 1; off < KWIN; off <<= 1) {
        float t = 0.f;
        if (tid < KWIN && tid >= off) t = sc[tid - off];
        __syncthreads();
        if (tid < KWIN && tid >= off) sc[tid] += t;
        __syncthreads();
    }
    if (tid < KWIN) {
        float c = (tid == KWIN - 1) ? 0.f : sc[KWIN - 2 - tid];
        wv[tid] = dots[tid] * __expf(c) * dte[tid];
    }
    __syncthreads();

    // ---- Phase C: y[p] = sum_s wv[s]*x[s,p] + D*xlast (rows L2-hot) ----
    {
        const float* base = hidden + ((size_t)b * T + s0 + hf * 64) * HIDD + h * PP + q;
        float acc = 0.f;
        for (int s = 0; s < 64; s++) acc += wv[hf * 64 + s] * base[(size_t)s * HIDD];
        part[hf][q] = acc;
    }
    __syncthreads();
    if (tid < PP) {
        float4 xw = xlast4[tid >> 2];
        float xl = (tid & 3) == 0 ? xw.x : (tid & 3) == 1 ? xw.y : (tid & 3) == 2 ? xw.z : xw.w;
        g_y[b][h][tid] = part[0][tid] + part[1][tid] + Dv[h] * xl;
    }
    __threadfence();                       // publish g_y to L2 before arrival
    __syncthreads();
    if (tid == 0) my_sh = atomicAdd(&g_cnt[b], 1u);

    // ---- Gate silu (independent of other blocks: overlaps barrier skew) ----
    {
        const float4* xl4 = (const float4*)(hidden + ((size_t)b * T + T - 1) * HIDD);
        const float4* w4  = (const float4*)(g_W + (size_t)warp * HIDD);
        float v = 0.f;
        #pragma unroll
        for (int k = 0; k < 8; k++) {
            float4 a = xl4[lane + 32 * k], w = w4[lane + 32 * k];
            v += a.x * w.x + a.y * w.y + a.z * w.z + a.w * w.w;
        }
        #pragma unroll
        for (int o = 16; o > 0; o >>= 1) v += __shfl_xor_sync(0xffffffffu, v, o);
        if (lane == 0) {
            float g = tanhf(v + g_bv[warp]);
            silu_sh[warp] = g / (1.f + __expf(-g));
        }
    }
    __syncthreads();

    // ---- Grid barrier: wait for all 8 blocks of this batch (monotonic,
    // reset-free: generation = my>>3, target = 8*(gen+1)) ----
    if (tid == 0) {
        unsigned target = ((my_sh >> 3) + 1u) << 3;
        volatile unsigned* c = &g_cnt[b];
        while (*c < target) {}
    }
    __syncthreads();
    __threadfence();                       // order subsequent g_y reads

    // ---- RMS over all 1024 gated values (redundant per block) ----
    float ssq = 0.f;
    #pragma unroll
    for (int k = 0; k < 4; k++) {
        int i = tid + k * 256;
        int hh = i >> 7;
        float z = __ldcg(&g_y[b][hh][i & 127]) * silu_sh[hh];
        ssq += z * z;
    }
    #pragma unroll
    for (int o = 16; o > 0; o >>= 1) ssq += __shfl_xor_sync(0xffffffffu, ssq, o);
    if (lane == 0) red[warp] = ssq;
    __syncthreads();
    if (tid == 0) {
        float s = 0.f;
        #pragma unroll
        for (int i = 0; i < 8; i++) s += red[i];
        scsh = rsqrtf(s / (float)HIDD + 1e-5f);
    }
    __syncthreads();

    // ---- Own-head normalized z, then 128x128 projection with Wreg ----
    if (tid < PP)
        zsh[tid] = __ldcg(&g_y[b][h][tid]) * silu_sh[h] * scsh * norm_w[h * PP + tid];
    __syncthreads();

    float acc = 0.f;
    #pragma unroll
    for (int i = 0; i < 64; i++) acc += Wreg[i] * zsh[hf * 64 + i];
    part[hf][q] = acc;
    __syncthreads();
    if (tid < PP)
        out[b * HIDD + h * PP + tid] = part[0][tid] + part[1][tid] + o_bv[h * PP + tid];
}

extern "C" void kernel_launch(void* const* d_in, const int* in_sizes, int n_in,
                              void* d_out, int out_size) {
    const float* hidden  = (const float*)d_in[0];
    const float* dt_W    = (const float*)d_in[1];
    const float* dt_b    = (const float*)d_in[2];
    const float* g_W     = (const float*)d_in[3];
    const float* g_bv    = (const float*)d_in[4];
    const float* A_log   = (const float*)d_in[5];
    const float* Dv      = (const float*)d_in[6];
    const float* dt_bias = (const float*)d_in[7];
    const float* norm_w  = (const float*)d_in[8];
    const float* o_W     = (const float*)d_in[9];
    const float* o_bv    = (const float*)d_in[10];

    int T = in_sizes[0] / (BB * HIDD);   // 4096

    k_fused<<<BB * HH, 256>>>(hidden, dt_W, dt_b, g_W, g_bv, A_log, Dv,
                              dt_bias, norm_w, o_W, o_bv, (float*)d_out, T);
}

// round 6
// speedup vs baseline: 1.0599x; 1.0599x over previous
#include <cuda_runtime.h>

#define BB   2
#define HH   8
#define PP   128
#define HIDD 1024
#define KWIN 64

__device__ float    g_dte [BB][KWIN][HH];
__device__ float    g_dots[BB][KWIN][HH];
__device__ float    g_y   [BB][HH][PP];
__device__ unsigned g_c1[BB], g_c2[BB];     // monotonic, never reset

__global__ void __launch_bounds__(256, 1)
k_fused(const float* __restrict__ hidden,
        const float* __restrict__ dt_W,
        const float* __restrict__ dt_b,
        const float* __restrict__ g_W,
        const float* __restrict__ g_bv,
        const float* __restrict__ A_log,
        const float* __restrict__ Dv,
        const float* __restrict__ dt_bias,
        const float* __restrict__ norm_w,
        const float* __restrict__ o_W,
        const float* __restrict__ o_bv,
        float* __restrict__ out, int T) {
    int b = blockIdx.x >> 3, h = blockIdx.x & 7;   // h doubles as row-group id
    int tid = threadIdx.x, warp = tid >> 5, lane = tid & 31;
    int q = tid & 127, hf = tid >> 7;
    int s0 = T - KWIN;

    __shared__ float    w_sh[HH * HIDD];    // all 8 dt_W rows (32 KB)
    __shared__ float    xlast_s[HIDD];      // full last hidden row (4 KB)
    __shared__ float    bias_sh[HH];
    __shared__ float    dteS[KWIN], sc[KWIN], wv[KWIN];
    __shared__ float    part[2][PP];
    __shared__ float    silu_sh[HH];
    __shared__ float    red[8];
    __shared__ float    scsh;
    __shared__ float    zsh[PP];
    __shared__ unsigned my1, my2;

    // ---- o_W prefetch: 512B/thread cold DRAM, consumed at the very end ----
    float Wreg[64];
    {
        const float* Wp = o_W + ((size_t)h * PP + hf * 64) * PP + q;
        #pragma unroll
        for (int i = 0; i < 64; i++) Wreg[i] = Wp[(size_t)i * PP];
    }

    {
        const float4* w4 = (const float4*)dt_W;
        float4* d4 = (float4*)w_sh;
        for (int i = tid; i < HH * HIDD / 4; i += 256) d4[i] = w4[i];
        const float4* xl4 = (const float4*)(hidden + ((size_t)b * T + T - 1) * HIDD);
        ((float4*)xlast_s)[tid] = xl4[tid];
        if (tid < HH) bias_sh[tid] = dt_b[tid] + dt_bias[tid];
    }
    __syncthreads();

    // ---- Phase 1: this block's 8 rows; ALL heads' dte + dots in one pass ----
    // float4 index i = lane + 32k: iteration k spans exactly head k's slice.
    {
        int s_loc = h * 8 + warp;                            // 0..63
        const float4* xr4 = (const float4*)(hidden + ((size_t)b * T + s0 + s_loc) * HIDD);
        const float4* xw4 = (const float4*)xlast_s;
        const float4* w4  = (const float4*)w_sh;
        float v[HH], dd[HH];
        #pragma unroll
        for (int k = 0; k < 8; k++) { v[k] = 0.f; dd[k] = 0.f; }
        #pragma unroll
        for (int k = 0; k < 8; k++) {
            float4 a  = xr4[lane + 32 * k];
            float4 xw = xw4[lane + 32 * k];
            dd[k] = a.x * xw.x + a.y * xw.y + a.z * xw.z + a.w * xw.w;
            #pragma unroll
            for (int hh = 0; hh < 8; hh++) {
                float4 w = w4[hh * 256 + lane + 32 * k];
                v[hh] += a.x * w.x + a.y * w.y + a.z * w.z + a.w * w.w;
            }
        }
        #pragma unroll
        for (int hh = 0; hh < 8; hh++) {
            #pragma unroll
            for (int o = 16; o > 0; o >>= 1) {
                v[hh]  += __shfl_xor_sync(0xffffffffu, v[hh],  o);
                dd[hh] += __shfl_xor_sync(0xffffffffu, dd[hh], o);
            }
        }
        if (lane < HH) {
            g_dte [b][s_loc][lane] = v[lane] + bias_sh[lane];
            g_dots[b][s_loc][lane] = dd[lane];
        }
    }
    __threadfence();
    __syncthreads();
    if (tid == 0) my1 = atomicAdd(&g_c1[b], 1u);

    // ---- Gate silu: independent work hidden in barrier skew ----
    {
        const float4* xl4 = (const float4*)xlast_s;
        const float4* w4  = (const float4*)(g_W + (size_t)warp * HIDD);
        float v = 0.f;
        #pragma unroll
        for (int k = 0; k < 8; k++) {
            float4 a = xl4[lane + 32 * k], w = w4[lane + 32 * k];
            v += a.x * w.x + a.y * w.y + a.z * w.z + a.w * w.w;
        }
        #pragma unroll
        for (int o = 16; o > 0; o >>= 1) v += __shfl_xor_sync(0xffffffffu, v, o);
        if (lane == 0) {
            float g = tanhf(v + g_bv[warp]);
            silu_sh[warp] = g / (1.f + __expf(-g));
        }
    }
    __syncthreads();

    // ---- Barrier 1 (monotonic, reset-free) ----
    if (tid == 0) {
        unsigned target = ((my1 >> 3) + 1u) << 3;
        volatile unsigned* c = &g_c1[b];
        while (*c < target) {}
    }
    __syncthreads();
    __threadfence();

    // ---- Phase 2: own-head suffix scan + window weights ----
    float Ah = -__expf(A_log[h]);
    if (tid < KWIN) dteS[tid] = __ldcg(&g_dte[b][tid][h]);
    __syncthreads();
    if (tid < KWIN) sc[tid] = dteS[KWIN - 1 - tid] * Ah;
    __syncthreads();
    for (int off = 1; off < KWIN; off <<= 1) {
        float t = 0.f;
        if (tid < KWIN && tid >= off) t = sc[tid - off];
        __syncthreads();
        if (tid < KWIN && tid >= off) sc[tid] += t;
        __syncthreads();
    }
    if (tid < KWIN) {
        float c = (tid == KWIN - 1) ? 0.f : sc[KWIN - 2 - tid];
        wv[tid] = __ldcg(&g_dots[b][tid][h]) * __expf(c) * dteS[tid];
    }
    __syncthreads();

    // ---- Phase 3: y[p] = sum_s wv[s]*x[s,p] + D*xlast (rows L2-hot) ----
    {
        const float* base = hidden + ((size_t)b * T + s0 + hf * 32) * HIDD + h * PP + q;
        float acc = 0.f;
        #pragma unroll
        for (int s = 0; s < 32; s++) acc += wv[hf * 32 + s] * base[(size_t)s * HIDD];
        part[hf][q] = acc;
    }
    __syncthreads();
    if (tid < PP)
        g_y[b][h][tid] = part[0][tid] + part[1][tid] + Dv[h] * xlast_s[h * PP + tid];
    __threadfence();
    __syncthreads();
    if (tid == 0) my2 = atomicAdd(&g_c2[b], 1u);
    __syncthreads();

    // ---- Barrier 2 ----
    if (tid == 0) {
        unsigned target = ((my2 >> 3) + 1u) << 3;
        volatile unsigned* c = &g_c2[b];
        while (*c < target) {}
    }
    __syncthreads();
    __threadfence();

    // ---- RMS over all 1024 gated values (redundant per block) ----
    float ssq = 0.f;
    #pragma unroll
    for (int k = 0; k < 4; k++) {
        int i = tid + k * 256;
        int hh = i >> 7;
        float z = __ldcg(&g_y[b][hh][i & 127]) * silu_sh[hh];
        ssq += z * z;
    }
    #pragma unroll
    for (int o = 16; o > 0; o >>= 1) ssq += __shfl_xor_sync(0xffffffffu, ssq, o);
    if (lane == 0) red[warp] = ssq;
    __syncthreads();
    if (tid == 0) {
        float s = 0.f;
        #pragma unroll
        for (int i = 0; i < 8; i++) s += red[i];
        scsh = rsqrtf(s / (float)HIDD + 1e-5f);
    }
    __syncthreads();

    // ---- Own-head z, then 128x128 projection with register-resident W ----
    if (tid < PP)
        zsh[tid] = __ldcg(&g_y[b][h][tid]) * silu_sh[h] * scsh * norm_w[h * PP + tid];
    __syncthreads();

    float acc = 0.f;
    #pragma unroll
    for (int i = 0; i < 64; i++) acc += Wreg[i] * zsh[hf * 64 + i];
    part[hf][q] = acc;
    __syncthreads();
    if (tid < PP)
        out[b * HIDD + h * PP + tid] = part[0][tid] + part[1][tid] + o_bv[h * PP + tid];
}

extern "C" void kernel_launch(void* const* d_in, const int* in_sizes, int n_in,
                              void* d_out, int out_size) {
    const float* hidden  = (const float*)d_in[0];
    const float* dt_W    = (const float*)d_in[1];
    const float* dt_b    = (const float*)d_in[2];
    const float* g_W     = (const float*)d_in[3];
    const float* g_bv    = (const float*)d_in[4];
    const float* A_log   = (const float*)d_in[5];
    const float* Dv      = (const float*)d_in[6];
    const float* dt_bias = (const float*)d_in[7];
    const float* norm_w  = (const float*)d_in[8];
    const float* o_W     = (const float*)d_in[9];
    const float* o_bv    = (const float*)d_in[10];

    int T = in_sizes[0] / (BB * HIDD);   // 4096

    k_fused<<<BB * HH, 256>>>(hidden, dt_W, dt_b, g_W, g_bv, A_log, Dv,
                              dt_bias, norm_w, o_W, o_bv, (float*)d_out, T);
}